// round 5
// baseline (speedup 1.0000x reference)
#include <cuda_runtime.h>
#include <cstdint>

typedef unsigned long long U64;

#define BATCH 4
#define CIN   2048
#define HW    50
#define CH    512
#define NA    9
#define NANCH (HW*HW*NA)     // 22500
#define PRE_K 2000
#define TOP_N 1000

// ---------------- device scratch (no allocation allowed) ----------------
__device__ __align__(16) float  g_h[BATCH*HW*HW*CH];     // conv out, [b][pix][ch]
__device__ U64    g_keys[BATCH*NANCH];
__device__ float4 g_deltas[BATCH*NANCH];
__device__ int    g_selidx[BATCH*PRE_K];
__device__ __align__(16) float4 g_boxes[BATCH*PRE_K];
__device__ U64    g_mask[BATCH*PRE_K*32];

// ---------------- f32x2 helpers ----------------
__device__ __forceinline__ U64 pack2(float lo, float hi) {
    U64 r; asm("mov.b64 %0, {%1,%2};" : "=l"(r) : "f"(lo), "f"(hi)); return r;
}
__device__ __forceinline__ void unpack2(U64 v, float &lo, float &hi) {
    asm("mov.b64 {%0,%1}, %2;" : "=f"(lo), "=f"(hi) : "l"(v));
}
__device__ __forceinline__ void fma2(U64 &d, U64 a, U64 b) {
    asm("fma.rn.f32x2 %0, %1, %2, %0;" : "+l"(d) : "l"(a), "l"(b));
}
__device__ __forceinline__ void add2(U64 &d, U64 a) {
    asm("add.rn.f32x2 %0, %0, %1;" : "+l"(d) : "l"(a));
}

// ============================================================================
// K1: 3x3 conv 2048->512 + bias + ReLU.  Block: 32 oc x 5 rows x 50 cols.
// Two-level accumulation: per-16-channel chunk accumulator merged into total
// (shortens fp32 error chains ~9x vs one sequential 18432-term sum).
// Static smem: Ws 18432 + Fs 25088 = 43520 B.
// ============================================================================
#define FS_STRIDE 56
__global__ void __launch_bounds__(256, 1)
conv_kernel(const float* __restrict__ feat,
            const float* __restrict__ wconv,
            const float* __restrict__ bconv)
{
    const int tid = threadIdx.x;
    const int x   = tid % 50;
    const int og  = tid / 50;          // 0..3 (only tid<200 compute)
    const int bx  = blockIdx.x;        // 0..39
    const int b   = bx / 10;
    const int y0  = (bx % 10) * 5;
    const int o0  = blockIdx.y * 32;

    __shared__ __align__(16) float Ws[16*9*32];          // [(c*9+k)*32 + o]
    __shared__ __align__(16) float Fs[16*7*FS_STRIDE];   // [c*392 + r*56 + xs]

    U64 acc[5][4];
#pragma unroll
    for (int r = 0; r < 5; ++r)
#pragma unroll
        for (int p = 0; p < 4; ++p) acc[r][p] = 0ull;

    for (int chunk = 0; chunk < CIN/16; ++chunk) {
        const int c0 = chunk * 16;
        __syncthreads();
        // W tile: 32 o x (16 c x 9) = 1152 float4
        for (int s = tid; s < 1152; s += 256) {
            int o = s / 36, v = s % 36;
            const float4 wv = *reinterpret_cast<const float4*>(
                wconv + (size_t)(o0 + o) * (CIN*9) + c0*9 + v*4);
            int ck = v * 4;
            Ws[(ck+0)*32 + o] = wv.x;
            Ws[(ck+1)*32 + o] = wv.y;
            Ws[(ck+2)*32 + o] = wv.z;
            Ws[(ck+3)*32 + o] = wv.w;
        }
        // F tile: 16 c x 7 rows x 52 valid cols (halo), stride 56
        for (int s = tid; s < 16*7*FS_STRIDE; s += 256) {
            int c   = s / (7*FS_STRIDE);
            int rem = s % (7*FS_STRIDE);
            int r   = rem / FS_STRIDE;
            int xs  = rem % FS_STRIDE;
            float v = 0.f;
            if (xs < 52) {
                int gy = y0 + r - 1;
                int gx = xs - 1;
                if ((unsigned)gy < 50u && (unsigned)gx < 50u)
                    v = feat[(size_t)(b*CIN + c0 + c) * (HW*HW) + gy*50 + gx];
            }
            Fs[s] = v;
        }
        __syncthreads();

        if (tid < 200) {
            // chunk-local accumulators (reset each chunk)
            U64 accC[5][4];
#pragma unroll
            for (int r = 0; r < 5; ++r)
#pragma unroll
                for (int p = 0; p < 4; ++p) accC[r][p] = 0ull;

#pragma unroll 1
            for (int c = 0; c < 16; ++c) {
#pragma unroll
                for (int ky = 0; ky < 3; ++ky) {
                    U64 f2[5][3];
#pragma unroll
                    for (int r = 0; r < 5; ++r)
#pragma unroll
                        for (int d = 0; d < 3; ++d) {
                            float fv = Fs[c*(7*FS_STRIDE) + (ky+r)*FS_STRIDE + x + d];
                            f2[r][d] = pack2(fv, fv);
                        }
                    const float* wb = &Ws[c*288 + og*8];
#pragma unroll
                    for (int kx = 0; kx < 3; ++kx) {
                        const int k = ky*3 + kx;
                        const ulonglong2 w01 = *reinterpret_cast<const ulonglong2*>(wb + k*32);
                        const ulonglong2 w23 = *reinterpret_cast<const ulonglong2*>(wb + k*32 + 4);
#pragma unroll
                        for (int row = 0; row < 5; ++row) {
                            U64 f = f2[row][kx];
                            fma2(accC[row][0], w01.x, f);
                            fma2(accC[row][1], w01.y, f);
                            fma2(accC[row][2], w23.x, f);
                            fma2(accC[row][3], w23.y, f);
                        }
                    }
                }
            }
            // merge chunk into total (short error chain)
#pragma unroll
            for (int r = 0; r < 5; ++r)
#pragma unroll
                for (int p = 0; p < 4; ++p) add2(acc[r][p], accC[r][p]);
        }
    }

    if (tid < 200) {
        const int ob = o0 + og*8;
        float bias[8];
#pragma unroll
        for (int j = 0; j < 8; ++j) bias[j] = bconv[ob + j];
#pragma unroll
        for (int row = 0; row < 5; ++row) {
            float o8[8];
#pragma unroll
            for (int p = 0; p < 4; ++p) unpack2(acc[row][p], o8[2*p], o8[2*p+1]);
#pragma unroll
            for (int j = 0; j < 8; ++j) o8[j] = fmaxf(o8[j] + bias[j], 0.f);
            float* dst = &g_h[((size_t)b*HW*HW + (y0+row)*50 + x) * CH + ob];
            *reinterpret_cast<float4*>(dst)     = make_float4(o8[0], o8[1], o8[2], o8[3]);
            *reinterpret_cast<float4*>(dst + 4) = make_float4(o8[4], o8[5], o8[6], o8[7]);
        }
    }
}

// ============================================================================
// K2: 1x1 cls/reg heads + 2-way softmax -> sort keys + deltas. 1 warp/pixel.
// ============================================================================
__global__ void heads_kernel(const float* __restrict__ w_cls,
                             const float* __restrict__ b_cls,
                             const float* __restrict__ w_reg,
                             const float* __restrict__ b_reg)
{
    const int wId  = blockIdx.x * 8 + (threadIdx.x >> 5);
    if (wId >= BATCH*HW*HW) return;
    const int lane = threadIdx.x & 31;
    const int wl   = threadIdx.x >> 5;
    const int b = wId / (HW*HW);
    const int p = wId % (HW*HW);

    float hreg[16];
    const float* hp = g_h + (size_t)wId * CH;
#pragma unroll
    for (int j = 0; j < 16; ++j) hreg[j] = hp[lane + j*32];

    __shared__ float dots[8][56];

    for (int o = 0; o < 54; ++o) {
        const float* wr = (o < 18) ? (w_cls + o*CH) : (w_reg + (o-18)*CH);
        float s = 0.f;
#pragma unroll
        for (int j = 0; j < 16; ++j) s += hreg[j] * wr[lane + j*32];
#pragma unroll
        for (int off = 16; off; off >>= 1) s += __shfl_down_sync(0xFFFFFFFFu, s, off);
        if (lane == 0)
            dots[wl][o] = s + ((o < 18) ? b_cls[o] : b_reg[o-18]);
    }
    __syncwarp();

    if (lane < 9) {
        const int a = lane;
        float l0 = dots[wl][a];
        float l1 = dots[wl][9 + a];
        float m  = fmaxf(l0, l1);
        float e0 = expf(l0 - m), e1 = expf(l1 - m);
        float fg = e1 / (e0 + e1);
        const int n = p * NA + a;
        unsigned kb = __float_as_uint(fg);     // fg in (0,1): bits order-preserving
        g_keys[b*NANCH + n] = ((U64)kb << 32) | (unsigned)(0xFFFFFFFFu - (unsigned)n);
        g_deltas[b*NANCH + n] = make_float4(dots[wl][18 + a*4 + 0],
                                            dots[wl][18 + a*4 + 1],
                                            dots[wl][18 + a*4 + 2],
                                            dots[wl][18 + a*4 + 3]);
    }
}

// ============================================================================
// K3: per-image exact top-2000 (8-pass radix select, keys unique) + bitonic
//     sort of 2048.  1 block/image, 1024 threads.
// ============================================================================
__global__ void select_kernel()
{
    const int b   = blockIdx.x;
    const int tid = threadIdx.x;
    __shared__ unsigned hist[256];
    __shared__ U64 s_keys[2048];
    __shared__ unsigned s_cnt;
    __shared__ U64 s_prefix;
    __shared__ unsigned s_target;

    const U64* keys = g_keys + (size_t)b * NANCH;
    if (tid == 0) { s_prefix = 0; s_target = PRE_K; s_cnt = 0; }
    U64 mask = 0;
    __syncthreads();

    for (int shift = 56; shift >= 0; shift -= 8) {
        if (tid < 256) hist[tid] = 0;
        __syncthreads();
        const U64 pfx = s_prefix;
        for (int i = tid; i < NANCH; i += 1024) {
            U64 k = keys[i];
            if ((k & mask) == pfx)
                atomicAdd(&hist[(unsigned)((k >> shift) & 255)], 1u);
        }
        __syncthreads();
        if (tid == 0) {
            unsigned cum = 0, tgt = s_target;
            for (int bin = 255; bin >= 0; --bin) {
                unsigned c = hist[bin];
                if (cum + c >= tgt) { s_prefix = pfx | ((U64)bin << shift); s_target = tgt - cum; break; }
                cum += c;
            }
        }
        mask |= (0xFFull << shift);
        __syncthreads();
    }

    const U64 kth = s_prefix;   // exact 2000th-largest key
    for (int i = tid; i < NANCH; i += 1024) {
        U64 k = keys[i];
        if (k >= kth) {
            unsigned pos = atomicAdd(&s_cnt, 1u);
            if (pos < 2048) s_keys[pos] = k;
        }
    }
    __syncthreads();
    for (unsigned i = s_cnt + tid; i < 2048; i += 1024) s_keys[i] = 0;  // pads last
    __syncthreads();

    for (int k = 2; k <= 2048; k <<= 1) {
        for (int j = k >> 1; j > 0; j >>= 1) {
            for (int i = tid; i < 2048; i += 1024) {
                int ixj = i ^ j;
                if (ixj > i) {
                    U64 a = s_keys[i], c = s_keys[ixj];
                    bool up = (i & k) == 0;              // descending
                    if (up ? (a < c) : (a > c)) { s_keys[i] = c; s_keys[ixj] = a; }
                }
            }
            __syncthreads();
        }
    }
    for (int r = tid; r < PRE_K; r += 1024) {
        U64 k = s_keys[r];
        g_selidx[b*PRE_K + r] = (int)(0xFFFFFFFFu - (unsigned)(k & 0xFFFFFFFFull));
    }
}

// ============================================================================
// K4: decode + clip selected boxes (reference math order).
// ============================================================================
__global__ void decode_kernel(const int* __restrict__ imh, const int* __restrict__ imw)
{
    int id = blockIdx.x * 256 + threadIdx.x;
    if (id >= BATCH*PRE_K) return;
    int b = id / PRE_K, r = id % PRE_K;
    int n = g_selidx[b*PRE_K + r];
    int a = n % NA, p = n / NA;
    int x = p % 50, y = p / 50;
    int si = a / 3, ri = a % 3;
    const float sizes[3]  = {128.f, 256.f, 512.f};
    const float ratios[3] = {0.5f, 1.f, 2.f};
    float sq = sqrtf(ratios[ri]);
    float ws = sizes[si] / sq;
    float hs = sizes[si] * sq;
    float cx = (x + 0.5f) * 32.f;
    float cy = (y + 0.5f) * 32.f;
    float x1 = cx - ws*0.5f, y1 = cy - hs*0.5f, x2 = cx + ws*0.5f, y2 = cy + hs*0.5f;
    float aw = x2 - x1, ah = y2 - y1;
    float acx = x1 + 0.5f*aw, acy = y1 + 0.5f*ah;
    float4 d = g_deltas[b*NANCH + n];
    float pcx = d.x*aw + acx;
    float pcy = d.y*ah + acy;
    float pw  = expf(fminf(d.z, 4.f)) * aw;
    float ph  = expf(fminf(d.w, 4.f)) * ah;
    int vi_w = imw[0], vi_h = imh[0];
    float W = (vi_w > 0 && vi_w < 1000000) ? (float)vi_w : reinterpret_cast<const float*>(imw)[0];
    float H = (vi_h > 0 && vi_h < 1000000) ? (float)vi_h : reinterpret_cast<const float*>(imh)[0];
    float bx1 = fminf(fmaxf(pcx - pw*0.5f, 0.f), W);
    float by1 = fminf(fmaxf(pcy - ph*0.5f, 0.f), H);
    float bx2 = fminf(fmaxf(pcx + pw*0.5f, 0.f), W);
    float by2 = fminf(fmaxf(pcy + ph*0.5f, 0.f), H);
    g_boxes[b*PRE_K + r] = make_float4(bx1, by1, bx2, by2);
}

// ============================================================================
// K5: IoU>0.7 bitmask. grid(32 jblk, 32 iblk, 4 b), 64 threads (i rows).
// ============================================================================
__global__ void iou_kernel()
{
    const int b  = blockIdx.z;
    const int i  = blockIdx.y * 64 + threadIdx.x;
    const int j0 = blockIdx.x * 64;
    __shared__ float4 jb[64];
    int jj = j0 + threadIdx.x;
    jb[threadIdx.x] = (jj < PRE_K) ? g_boxes[b*PRE_K + jj] : make_float4(0.f,0.f,0.f,0.f);
    __syncthreads();
    if (i >= PRE_K) return;
    float4 bi = g_boxes[b*PRE_K + i];
    float ai = (bi.z - bi.x) * (bi.w - bi.y);
    U64 w = 0;
#pragma unroll 4
    for (int t = 0; t < 64; ++t) {
        float4 bj = jb[t];
        float aj = (bj.z - bj.x)*(bj.w - bj.y);
        float lx = fmaxf(bi.x, bj.x), ly = fmaxf(bi.y, bj.y);
        float rx = fminf(bi.z, bj.z), ry = fminf(bi.w, bj.w);
        float iw = fmaxf(rx - lx, 0.f), ih = fmaxf(ry - ly, 0.f);
        float inter = iw * ih;
        float iou = inter / (ai + aj - inter + 1e-9f);
        if (iou > 0.7f) w |= (1ull << t);
    }
    g_mask[((size_t)b*PRE_K + i)*32 + blockIdx.x] = w;
}

// ============================================================================
// K6: serial NMS scan (1 warp/image) + NEG_INF-fill output gather.
// ============================================================================
__global__ void nms_kernel(float* __restrict__ out)
{
    const int b = blockIdx.x;
    const int lane = threadIdx.x;   // 32 threads
    U64 remv = 0;
    __shared__ unsigned char keep[PRE_K];
    const U64* mbase = g_mask + (size_t)b*PRE_K*32;
    for (int i = 0; i < PRE_K; ++i) {
        U64 m = mbase[(size_t)i*32 + lane];   // unconditional: hides latency
        int w = i >> 6, bit = i & 63;
        U64 rw = __shfl_sync(0xFFFFFFFFu, remv, w);
        bool kept = !((rw >> bit) & 1ull);
        if (kept) remv |= m;
        if (lane == 0) keep[i] = kept;
    }
    __syncwarp();
    if (lane == 0) {
        float4* ob = reinterpret_cast<float4*>(out) + b*TOP_N;
        int r = 0;
        for (int i = 0; i < PRE_K && r < TOP_N; ++i)
            if (keep[i]) ob[r++] = g_boxes[b*PRE_K + i];
        for (int i = 0; i < PRE_K && r < TOP_N; ++i)
            if (!keep[i]) ob[r++] = g_boxes[b*PRE_K + i];   // NEG_INF fill, idx asc
    }
}

// ============================================================================
extern "C" void kernel_launch(void* const* d_in, const int* in_sizes, int n_in,
                              void* d_out, int out_size)
{
    const float* feat   = (const float*)d_in[0];
    const float* w_conv = (const float*)d_in[1];
    const float* b_conv = (const float*)d_in[2];
    const float* w_cls  = (const float*)d_in[3];
    const float* b_cls  = (const float*)d_in[4];
    const float* w_reg  = (const float*)d_in[5];
    const float* b_reg  = (const float*)d_in[6];
    const int*   img_h  = (const int*)d_in[7];
    const int*   img_w  = (const int*)d_in[8];
    float* out = (float*)d_out;

    conv_kernel<<<dim3(40, 16), 256>>>(feat, w_conv, b_conv);
    heads_kernel<<<(BATCH*HW*HW + 7) / 8, 256>>>(w_cls, b_cls, w_reg, b_reg);
    select_kernel<<<BATCH, 1024>>>();
    decode_kernel<<<(BATCH*PRE_K + 255) / 256, 256>>>(img_h, img_w);
    iou_kernel<<<dim3(32, 32, BATCH), 64>>>();
    nms_kernel<<<BATCH, 32>>>(out);
}

// round 6
// speedup vs baseline: 1.4315x; 1.4315x over previous
#include <cuda_runtime.h>
#include <cstdint>

typedef unsigned long long U64;

#define BATCH 4
#define CIN   2048
#define HW    50
#define CH    512
#define NA    9
#define NANCH (HW*HW*NA)     // 22500
#define PRE_K 2000
#define TOP_N 1000

// ---------------- device scratch (no allocation allowed) ----------------
__device__ __align__(16) float  g_h[BATCH*HW*HW*CH];     // conv out, [b][pix][ch]
__device__ U64    g_keys[BATCH*NANCH];
__device__ float4 g_deltas[BATCH*NANCH];
__device__ int    g_selidx[BATCH*PRE_K];
__device__ __align__(16) float4 g_boxes[BATCH*PRE_K];
__device__ U64    g_mask[BATCH*PRE_K*32];

// ---------------- f32x2 helpers ----------------
__device__ __forceinline__ U64 pack2(float lo, float hi) {
    U64 r; asm("mov.b64 %0, {%1,%2};" : "=l"(r) : "f"(lo), "f"(hi)); return r;
}
__device__ __forceinline__ void unpack2(U64 v, float &lo, float &hi) {
    asm("mov.b64 {%0,%1}, %2;" : "=f"(lo), "=f"(hi) : "l"(v));
}
__device__ __forceinline__ void fma2(U64 &d, U64 a, U64 b) {
    asm("fma.rn.f32x2 %0, %1, %2, %0;" : "+l"(d) : "l"(a), "l"(b));
}
__device__ __forceinline__ void add2(U64 &d, U64 a) {
    asm("add.rn.f32x2 %0, %0, %1;" : "+l"(d) : "l"(a));
}

// ============================================================================
// K1: 3x3 conv 2048->512 + bias + ReLU.  Block: 32 oc x 5 rows x 50 cols.
// Two-level accumulation (precision-critical: per-16-ch chunk accumulator).
// Restructured vs R5: kx-outer rolling f-window (f2[7]) to cut regs to ~112
// -> __launch_bounds__(256,2) -> 2 blocks/SM -> 4 warps/SMSP.
// Static smem: Ws 18432 + Fs 25088 = 43520 B/block (2 blocks fit in SM smem).
// ============================================================================
#define FS_STRIDE 56
__global__ void __launch_bounds__(256, 2)
conv_kernel(const float* __restrict__ feat,
            const float* __restrict__ wconv,
            const float* __restrict__ bconv)
{
    const int tid = threadIdx.x;
    const int x   = tid % 50;
    const int og  = tid / 50;          // 0..3 (only tid<200 compute)
    const int bx  = blockIdx.x;        // 0..39
    const int b   = bx / 10;
    const int y0  = (bx % 10) * 5;
    const int o0  = blockIdx.y * 32;

    __shared__ __align__(16) float Ws[16*9*32];          // [(c*9+k)*32 + o]
    __shared__ __align__(16) float Fs[16*7*FS_STRIDE];   // [c*392 + r*56 + xs]

    U64 acc[5][4];
#pragma unroll
    for (int r = 0; r < 5; ++r)
#pragma unroll
        for (int p = 0; p < 4; ++p) acc[r][p] = 0ull;

    for (int chunk = 0; chunk < CIN/16; ++chunk) {
        const int c0 = chunk * 16;
        __syncthreads();
        // W tile: 32 o x (16 c x 9) = 1152 float4
        for (int s = tid; s < 1152; s += 256) {
            int o = s / 36, v = s % 36;
            const float4 wv = *reinterpret_cast<const float4*>(
                wconv + (size_t)(o0 + o) * (CIN*9) + c0*9 + v*4);
            int ck = v * 4;
            Ws[(ck+0)*32 + o] = wv.x;
            Ws[(ck+1)*32 + o] = wv.y;
            Ws[(ck+2)*32 + o] = wv.z;
            Ws[(ck+3)*32 + o] = wv.w;
        }
        // F tile: 16 c x 7 rows x 52 valid cols (halo), stride 56
        for (int s = tid; s < 16*7*FS_STRIDE; s += 256) {
            int c   = s / (7*FS_STRIDE);
            int rem = s % (7*FS_STRIDE);
            int r   = rem / FS_STRIDE;
            int xs  = rem % FS_STRIDE;
            float v = 0.f;
            if (xs < 52) {
                int gy = y0 + r - 1;
                int gx = xs - 1;
                if ((unsigned)gy < 50u && (unsigned)gx < 50u)
                    v = feat[(size_t)(b*CIN + c0 + c) * (HW*HW) + gy*50 + gx];
            }
            Fs[s] = v;
        }
        __syncthreads();

        if (tid < 200) {
            // chunk-local accumulators (reset each chunk) — precision-critical
            U64 accC[5][4];
#pragma unroll
            for (int r = 0; r < 5; ++r)
#pragma unroll
                for (int p = 0; p < 4; ++p) accC[r][p] = 0ull;

#pragma unroll 1
            for (int c = 0; c < 16; ++c) {
                const float* fcol = &Fs[c*(7*FS_STRIDE) + x];
                const float* wb   = &Ws[c*288 + og*8];
#pragma unroll
                for (int kx = 0; kx < 3; ++kx) {
                    // rolling 7-row input window for this kx column
                    U64 f2[7];
#pragma unroll
                    for (int r = 0; r < 7; ++r) {
                        float fv = fcol[r*FS_STRIDE + kx];
                        f2[r] = pack2(fv, fv);
                    }
#pragma unroll
                    for (int ky = 0; ky < 3; ++ky) {
                        const int k = ky*3 + kx;
                        const ulonglong2 w01 = *reinterpret_cast<const ulonglong2*>(wb + k*32);
                        const ulonglong2 w23 = *reinterpret_cast<const ulonglong2*>(wb + k*32 + 4);
#pragma unroll
                        for (int row = 0; row < 5; ++row) {
                            U64 f = f2[row + ky];
                            fma2(accC[row][0], w01.x, f);
                            fma2(accC[row][1], w01.y, f);
                            fma2(accC[row][2], w23.x, f);
                            fma2(accC[row][3], w23.y, f);
                        }
                    }
                }
            }
            // merge chunk into total (short error chain)
#pragma unroll
            for (int r = 0; r < 5; ++r)
#pragma unroll
                for (int p = 0; p < 4; ++p) add2(acc[r][p], accC[r][p]);
        }
    }

    if (tid < 200) {
        const int ob = o0 + og*8;
        float bias[8];
#pragma unroll
        for (int j = 0; j < 8; ++j) bias[j] = bconv[ob + j];
#pragma unroll
        for (int row = 0; row < 5; ++row) {
            float o8[8];
#pragma unroll
            for (int p = 0; p < 4; ++p) unpack2(acc[row][p], o8[2*p], o8[2*p+1]);
#pragma unroll
            for (int j = 0; j < 8; ++j) o8[j] = fmaxf(o8[j] + bias[j], 0.f);
            float* dst = &g_h[((size_t)b*HW*HW + (y0+row)*50 + x) * CH + ob];
            *reinterpret_cast<float4*>(dst)     = make_float4(o8[0], o8[1], o8[2], o8[3]);
            *reinterpret_cast<float4*>(dst + 4) = make_float4(o8[4], o8[5], o8[6], o8[7]);
        }
    }
}

// ============================================================================
// K2: 1x1 cls/reg heads + 2-way softmax -> sort keys + deltas. 1 warp/pixel.
// ============================================================================
__global__ void heads_kernel(const float* __restrict__ w_cls,
                             const float* __restrict__ b_cls,
                             const float* __restrict__ w_reg,
                             const float* __restrict__ b_reg)
{
    const int wId  = blockIdx.x * 8 + (threadIdx.x >> 5);
    if (wId >= BATCH*HW*HW) return;
    const int lane = threadIdx.x & 31;
    const int wl   = threadIdx.x >> 5;
    const int b = wId / (HW*HW);
    const int p = wId % (HW*HW);

    float hreg[16];
    const float* hp = g_h + (size_t)wId * CH;
#pragma unroll
    for (int j = 0; j < 16; ++j) hreg[j] = hp[lane + j*32];

    __shared__ float dots[8][56];

    for (int o = 0; o < 54; ++o) {
        const float* wr = (o < 18) ? (w_cls + o*CH) : (w_reg + (o-18)*CH);
        float s = 0.f;
#pragma unroll
        for (int j = 0; j < 16; ++j) s += hreg[j] * wr[lane + j*32];
#pragma unroll
        for (int off = 16; off; off >>= 1) s += __shfl_down_sync(0xFFFFFFFFu, s, off);
        if (lane == 0)
            dots[wl][o] = s + ((o < 18) ? b_cls[o] : b_reg[o-18]);
    }
    __syncwarp();

    if (lane < 9) {
        const int a = lane;
        float l0 = dots[wl][a];
        float l1 = dots[wl][9 + a];
        float m  = fmaxf(l0, l1);
        float e0 = expf(l0 - m), e1 = expf(l1 - m);
        float fg = e1 / (e0 + e1);
        const int n = p * NA + a;
        unsigned kb = __float_as_uint(fg);     // fg in (0,1): bits order-preserving
        g_keys[b*NANCH + n] = ((U64)kb << 32) | (unsigned)(0xFFFFFFFFu - (unsigned)n);
        g_deltas[b*NANCH + n] = make_float4(dots[wl][18 + a*4 + 0],
                                            dots[wl][18 + a*4 + 1],
                                            dots[wl][18 + a*4 + 2],
                                            dots[wl][18 + a*4 + 3]);
    }
}

// ============================================================================
// K3: per-image exact top-2000 (8-pass radix select, keys unique) + bitonic
//     sort of 2048.  1 block/image, 1024 threads.
// ============================================================================
__global__ void select_kernel()
{
    const int b   = blockIdx.x;
    const int tid = threadIdx.x;
    __shared__ unsigned hist[256];
    __shared__ U64 s_keys[2048];
    __shared__ unsigned s_cnt;
    __shared__ U64 s_prefix;
    __shared__ unsigned s_target;

    const U64* keys = g_keys + (size_t)b * NANCH;
    if (tid == 0) { s_prefix = 0; s_target = PRE_K; s_cnt = 0; }
    U64 mask = 0;
    __syncthreads();

    for (int shift = 56; shift >= 0; shift -= 8) {
        if (tid < 256) hist[tid] = 0;
        __syncthreads();
        const U64 pfx = s_prefix;
        for (int i = tid; i < NANCH; i += 1024) {
            U64 k = keys[i];
            if ((k & mask) == pfx)
                atomicAdd(&hist[(unsigned)((k >> shift) & 255)], 1u);
        }
        __syncthreads();
        if (tid == 0) {
            unsigned cum = 0, tgt = s_target;
            for (int bin = 255; bin >= 0; --bin) {
                unsigned c = hist[bin];
                if (cum + c >= tgt) { s_prefix = pfx | ((U64)bin << shift); s_target = tgt - cum; break; }
                cum += c;
            }
        }
        mask |= (0xFFull << shift);
        __syncthreads();
    }

    const U64 kth = s_prefix;   // exact 2000th-largest key
    for (int i = tid; i < NANCH; i += 1024) {
        U64 k = keys[i];
        if (k >= kth) {
            unsigned pos = atomicAdd(&s_cnt, 1u);
            if (pos < 2048) s_keys[pos] = k;
        }
    }
    __syncthreads();
    for (unsigned i = s_cnt + tid; i < 2048; i += 1024) s_keys[i] = 0;  // pads last
    __syncthreads();

    for (int k = 2; k <= 2048; k <<= 1) {
        for (int j = k >> 1; j > 0; j >>= 1) {
            for (int i = tid; i < 2048; i += 1024) {
                int ixj = i ^ j;
                if (ixj > i) {
                    U64 a = s_keys[i], c = s_keys[ixj];
                    bool up = (i & k) == 0;              // descending
                    if (up ? (a < c) : (a > c)) { s_keys[i] = c; s_keys[ixj] = a; }
                }
            }
            __syncthreads();
        }
    }
    for (int r = tid; r < PRE_K; r += 1024) {
        U64 k = s_keys[r];
        g_selidx[b*PRE_K + r] = (int)(0xFFFFFFFFu - (unsigned)(k & 0xFFFFFFFFull));
    }
}

// ============================================================================
// K4: decode + clip selected boxes (reference math order).
// ============================================================================
__global__ void decode_kernel(const int* __restrict__ imh, const int* __restrict__ imw)
{
    int id = blockIdx.x * 256 + threadIdx.x;
    if (id >= BATCH*PRE_K) return;
    int b = id / PRE_K, r = id % PRE_K;
    int n = g_selidx[b*PRE_K + r];
    int a = n % NA, p = n / NA;
    int x = p % 50, y = p / 50;
    int si = a / 3, ri = a % 3;
    const float sizes[3]  = {128.f, 256.f, 512.f};
    const float ratios[3] = {0.5f, 1.f, 2.f};
    float sq = sqrtf(ratios[ri]);
    float ws = sizes[si] / sq;
    float hs = sizes[si] * sq;
    float cx = (x + 0.5f) * 32.f;
    float cy = (y + 0.5f) * 32.f;
    float x1 = cx - ws*0.5f, y1 = cy - hs*0.5f, x2 = cx + ws*0.5f, y2 = cy + hs*0.5f;
    float aw = x2 - x1, ah = y2 - y1;
    float acx = x1 + 0.5f*aw, acy = y1 + 0.5f*ah;
    float4 d = g_deltas[b*NANCH + n];
    float pcx = d.x*aw + acx;
    float pcy = d.y*ah + acy;
    float pw  = expf(fminf(d.z, 4.f)) * aw;
    float ph  = expf(fminf(d.w, 4.f)) * ah;
    int vi_w = imw[0], vi_h = imh[0];
    float W = (vi_w > 0 && vi_w < 1000000) ? (float)vi_w : reinterpret_cast<const float*>(imw)[0];
    float H = (vi_h > 0 && vi_h < 1000000) ? (float)vi_h : reinterpret_cast<const float*>(imh)[0];
    float bx1 = fminf(fmaxf(pcx - pw*0.5f, 0.f), W);
    float by1 = fminf(fmaxf(pcy - ph*0.5f, 0.f), H);
    float bx2 = fminf(fmaxf(pcx + pw*0.5f, 0.f), W);
    float by2 = fminf(fmaxf(pcy + ph*0.5f, 0.f), H);
    g_boxes[b*PRE_K + r] = make_float4(bx1, by1, bx2, by2);
}

// ============================================================================
// K5: IoU>0.7 bitmask. grid(32 jblk, 32 iblk, 4 b), 64 threads (i rows).
// ============================================================================
__global__ void iou_kernel()
{
    const int b  = blockIdx.z;
    const int i  = blockIdx.y * 64 + threadIdx.x;
    const int j0 = blockIdx.x * 64;
    __shared__ float4 jb[64];
    int jj = j0 + threadIdx.x;
    jb[threadIdx.x] = (jj < PRE_K) ? g_boxes[b*PRE_K + jj] : make_float4(0.f,0.f,0.f,0.f);
    __syncthreads();
    if (i >= PRE_K) return;
    float4 bi = g_boxes[b*PRE_K + i];
    float ai = (bi.z - bi.x) * (bi.w - bi.y);
    U64 w = 0;
#pragma unroll 4
    for (int t = 0; t < 64; ++t) {
        float4 bj = jb[t];
        float aj = (bj.z - bj.x)*(bj.w - bj.y);
        float lx = fmaxf(bi.x, bj.x), ly = fmaxf(bi.y, bj.y);
        float rx = fminf(bi.z, bj.z), ry = fminf(bi.w, bj.w);
        float iw = fmaxf(rx - lx, 0.f), ih = fmaxf(ry - ly, 0.f);
        float inter = iw * ih;
        float iou = inter / (ai + aj - inter + 1e-9f);
        if (iou > 0.7f) w |= (1ull << t);
    }
    g_mask[((size_t)b*PRE_K + i)*32 + blockIdx.x] = w;
}

// ============================================================================
// K6: serial NMS scan (1 warp/image) + NEG_INF-fill output gather.
// ============================================================================
__global__ void nms_kernel(float* __restrict__ out)
{
    const int b = blockIdx.x;
    const int lane = threadIdx.x;   // 32 threads
    U64 remv = 0;
    __shared__ unsigned char keep[PRE_K];
    const U64* mbase = g_mask + (size_t)b*PRE_K*32;
    for (int i = 0; i < PRE_K; ++i) {
        U64 m = mbase[(size_t)i*32 + lane];   // unconditional: hides latency
        int w = i >> 6, bit = i & 63;
        U64 rw = __shfl_sync(0xFFFFFFFFu, remv, w);
        bool kept = !((rw >> bit) & 1ull);
        if (kept) remv |= m;
        if (lane == 0) keep[i] = kept;
    }
    __syncwarp();
    if (lane == 0) {
        float4* ob = reinterpret_cast<float4*>(out) + b*TOP_N;
        int r = 0;
        for (int i = 0; i < PRE_K && r < TOP_N; ++i)
            if (keep[i]) ob[r++] = g_boxes[b*PRE_K + i];
        for (int i = 0; i < PRE_K && r < TOP_N; ++i)
            if (!keep[i]) ob[r++] = g_boxes[b*PRE_K + i];   // NEG_INF fill, idx asc
    }
}

// ============================================================================
extern "C" void kernel_launch(void* const* d_in, const int* in_sizes, int n_in,
                              void* d_out, int out_size)
{
    const float* feat   = (const float*)d_in[0];
    const float* w_conv = (const float*)d_in[1];
    const float* b_conv = (const float*)d_in[2];
    const float* w_cls  = (const float*)d_in[3];
    const float* b_cls  = (const float*)d_in[4];
    const float* w_reg  = (const float*)d_in[5];
    const float* b_reg  = (const float*)d_in[6];
    const int*   img_h  = (const int*)d_in[7];
    const int*   img_w  = (const int*)d_in[8];
    float* out = (float*)d_out;

    conv_kernel<<<dim3(40, 16), 256>>>(feat, w_conv, b_conv);
    heads_kernel<<<(BATCH*HW*HW + 7) / 8, 256>>>(w_cls, b_cls, w_reg, b_reg);
    select_kernel<<<BATCH, 1024>>>();
    decode_kernel<<<(BATCH*PRE_K + 255) / 256, 256>>>(img_h, img_w);
    iou_kernel<<<dim3(32, 32, BATCH), 64>>>();
    nms_kernel<<<BATCH, 32>>>(out);
}